// round 11
// baseline (speedup 1.0000x reference)
#include <cuda_runtime.h>
#include <math.h>

#define NB 64
#define NS 257
#define ND 768
#define NH 12
#define HD 64
#define NTOK (NB*NS)          /* 16448 */
#define NQKV (NTOK*ND)        /* 12632064 */
#define NBH (NB*NH)           /* 768 */
#define EPSV 1e-10f
#define LAMDA 0.475f

// GEMM smem layout strides (uint2 units)
#define KG_STR 132
#define KH_STR 536
#define BUF_STR 1072

// ---------------- device scratch ----------------
__device__ float g_qkv[3*NQKV];            // q | k | v, each (B,H,S,HD)
__device__ float g_ctx[NQKV];              // (B,S,D)
__device__ float g_ent[NBH*NS];            // entropy row, [0]=1
__device__ float g_loss1[NBH];
__device__ float g_loss2[NBH];
__device__ float g_part1[(size_t)NBH*256*8];  // p1 layer-2 partial dots
__device__ float g_part2[(size_t)NBH*64*8];   // p2 layer-2 partial dots

// ---------------- tf32 helpers ----------------
__device__ __forceinline__ unsigned f2tf32(float x){
    unsigned r; asm("cvt.rna.tf32.f32 %0, %1;" : "=r"(r) : "f"(x)); return r;
}
__device__ __forceinline__ void mma_tf32(float* c,
    unsigned a0, unsigned a1, unsigned a2, unsigned a3,
    unsigned b0, unsigned b1)
{
    asm volatile(
      "mma.sync.aligned.m16n8k8.row.col.f32.tf32.tf32.f32 "
      "{%0,%1,%2,%3},{%4,%5,%6,%7},{%8,%9},{%0,%1,%2,%3};"
      : "+f"(c[0]), "+f"(c[1]), "+f"(c[2]), "+f"(c[3])
      : "r"(a0), "r"(a1), "r"(a2), "r"(a3), "r"(b0), "r"(b1));
}

// =====================================================================
// Tensor-core tf32 GEMM: BM=128, BN=128, BK=16, 256 threads, 2-stage smem.
// AMODE 0: A row-major [M,K] (guarded)
// AMODE 2: p1 feature gather (row m -> bh,t in k tensor), lda=64
// AMODE 3: p2 merged-patch gather (K=256 -> q,d decomposition)
// EMODE 0: C row-major + bias
// EMODE 3: fused relu + dot with W2 -> per-(row, col-slice) partials in C
// =====================================================================
template<int AMODE, int EMODE>
__global__ void __launch_bounds__(256)
gemm_tc(const float* __restrict__ A, const float* __restrict__ W,
        const float* __restrict__ bias, const float* __restrict__ W2,
        float* __restrict__ C, int M, int N, int K)
{
    __shared__ uint2 AsI[2*BUF_STR];
    __shared__ uint2 BsI[2*BUF_STR];

    const int tid  = threadIdx.x;
    const int lane = tid & 31;
    const int warp = tid >> 5;
    const int g    = lane >> 2;
    const int t4   = lane & 3;
    const int wm   = (warp & 3) * 32;
    const int wn   = (warp >> 2) * 64;
    const int mBase = blockIdx.y * 128;
    const int nBase = blockIdx.x * 128;

    const int aRow = tid >> 1;
    const int aKh  = tid & 1;
    const int bKh  = warp >> 2;
    const int bKg  = warp & 3;
    const int bN   = (tid & 31) * 4;

    long aOff = -1;
    int  rowbase = 0, pr2 = 0, pc2 = 0;
    if (AMODE == 0) {
        int m = mBase + aRow;
        if (m < M) aOff = (long)m * K;
    } else if (AMODE == 2) {
        int m  = mBase + aRow;
        int bh = m >> 8, t = m & 255;
        aOff = ((long)bh * NS + 1 + t) * HD;
    } else { // AMODE 3
        int m  = mBase + aRow;
        int bh = m >> 6, patch = m & 63;
        rowbase = bh * NS + 1;
        pr2 = patch >> 3; pc2 = patch & 7;
    }

    float ra[8], rb[8];

    auto loadAB = [&](int k0) {
        if (AMODE == 3) {
            int kk = k0 + aKh*8;
            int q = kk >> 6, d = kk & 63;
            int token = (2*pr2 + (q >> 1)) * 16 + 2*pc2 + (q & 1);
            const float4* p = (const float4*)(A + ((long)(rowbase + token)) * HD + d);
            float4 v0 = p[0], v1 = p[1];
            ra[0]=v0.x; ra[1]=v0.y; ra[2]=v0.z; ra[3]=v0.w;
            ra[4]=v1.x; ra[5]=v1.y; ra[6]=v1.z; ra[7]=v1.w;
        } else {
            if (aOff >= 0) {
                const float4* p = (const float4*)(A + aOff + k0 + aKh*8);
                float4 v0 = p[0], v1 = p[1];
                ra[0]=v0.x; ra[1]=v0.y; ra[2]=v0.z; ra[3]=v0.w;
                ra[4]=v1.x; ra[5]=v1.y; ra[6]=v1.z; ra[7]=v1.w;
            } else {
                #pragma unroll
                for (int j = 0; j < 8; ++j) ra[j] = 0.f;
            }
        }
        const float4 w0 = *(const float4*)(W + (long)(k0 + bKh*8 + bKg)     * N + nBase + bN);
        const float4 w1 = *(const float4*)(W + (long)(k0 + bKh*8 + bKg + 4) * N + nBase + bN);
        rb[0]=w0.x; rb[1]=w0.y; rb[2]=w0.z; rb[3]=w0.w;
        rb[4]=w1.x; rb[5]=w1.y; rb[6]=w1.z; rb[7]=w1.w;
    };
    auto stageAB = [&](int buf) {
        uint2* Ap = AsI + buf*BUF_STR + aKh*KH_STR + aRow;
        #pragma unroll
        for (int j = 0; j < 4; ++j)
            Ap[j*KG_STR] = make_uint2(f2tf32(ra[j]), f2tf32(ra[j+4]));
        uint2* Bp = BsI + buf*BUF_STR + bKh*KH_STR + bKg*KG_STR + bN;
        #pragma unroll
        for (int j = 0; j < 4; ++j)
            Bp[j] = make_uint2(f2tf32(rb[j]), f2tf32(rb[j+4]));
    };

    float acc[2][8][4];
    #pragma unroll
    for (int mt = 0; mt < 2; ++mt)
        #pragma unroll
        for (int nt = 0; nt < 8; ++nt)
            #pragma unroll
            for (int i = 0; i < 4; ++i) acc[mt][nt][i] = 0.f;

    loadAB(0);
    stageAB(0);
    __syncthreads();
    int cur = 0;

    for (int k0 = 0; k0 < K; k0 += 16) {
        const bool more = (k0 + 16) < K;
        if (more) loadAB(k0 + 16);

        #pragma unroll
        for (int ks = 0; ks < 2; ++ks) {
            const uint2* Ab = AsI + cur*BUF_STR + ks*KH_STR + t4*KG_STR;
            uint2 a00 = Ab[wm + g];
            uint2 a01 = Ab[wm + g + 8];
            uint2 a10 = Ab[wm + 16 + g];
            uint2 a11 = Ab[wm + 16 + g + 8];
            const uint2* Bb = BsI + cur*BUF_STR + ks*KH_STR + t4*KG_STR + wn;
            #pragma unroll
            for (int nt = 0; nt < 8; ++nt) {
                uint2 bb = Bb[nt*8 + g];
                mma_tf32(acc[0][nt], a00.x, a01.x, a00.y, a01.y, bb.x, bb.y);
                mma_tf32(acc[1][nt], a10.x, a11.x, a10.y, a11.y, bb.x, bb.y);
            }
        }
        if (more) {
            stageAB(cur ^ 1);
            __syncthreads();
            cur ^= 1;
        }
    }

    // ---- epilogue
    if (EMODE == 3) {
        float part[2][2] = {{0.f, 0.f}, {0.f, 0.f}};
        #pragma unroll
        for (int nt = 0; nt < 8; ++nt) {
            int c0 = nBase + wn + nt * 8 + 2 * t4;
            float bi0 = __ldg(bias + c0),  bi1 = __ldg(bias + c0 + 1);
            float w20 = __ldg(W2 + c0),    w21 = __ldg(W2 + c0 + 1);
            #pragma unroll
            for (int mt = 0; mt < 2; ++mt) {
                part[mt][0] = fmaf(fmaxf(acc[mt][nt][0] + bi0, 0.f), w20, part[mt][0]);
                part[mt][0] = fmaf(fmaxf(acc[mt][nt][1] + bi1, 0.f), w21, part[mt][0]);
                part[mt][1] = fmaf(fmaxf(acc[mt][nt][2] + bi0, 0.f), w20, part[mt][1]);
                part[mt][1] = fmaf(fmaxf(acc[mt][nt][3] + bi1, 0.f), w21, part[mt][1]);
            }
        }
        #pragma unroll
        for (int mt = 0; mt < 2; ++mt)
            #pragma unroll
            for (int hf = 0; hf < 2; ++hf) {
                float v = part[mt][hf];
                v += __shfl_xor_sync(0xffffffffu, v, 1);
                v += __shfl_xor_sync(0xffffffffu, v, 2);
                part[mt][hf] = v;
            }
        if (t4 == 0) {
            #pragma unroll
            for (int mt = 0; mt < 2; ++mt)
                #pragma unroll
                for (int hf = 0; hf < 2; ++hf) {
                    long m = mBase + wm + mt * 16 + g + hf * 8;
                    C[m * 8 + blockIdx.x * 2 + (warp >> 2)] = part[mt][hf];
                }
        }
    } else { // EMODE 0
        #pragma unroll
        for (int mt = 0; mt < 2; ++mt) {
            int r0 = mBase + wm + mt * 16 + g;
            #pragma unroll
            for (int nt = 0; nt < 8; ++nt) {
                int c0 = nBase + wn + nt * 8 + 2 * t4;
                #pragma unroll
                for (int half = 0; half < 2; ++half) {
                    int m = r0 + half * 8;
                    if (m < M) {
                        float* cp = C + (long)m * N + c0;
                        cp[0] = acc[mt][nt][half*2 + 0] + bias[c0];
                        cp[1] = acc[mt][nt][half*2 + 1] + bias[c0 + 1];
                    }
                }
            }
        }
    }
}

// =====================================================================
// QKV projection. mode 1: K only, grid (6,129).
// mode 0: Q and V, grid (12,129), blockIdx.x/6 -> 0:Q, 1:V.
// =====================================================================
__global__ void __launch_bounds__(256)
gemm_qkv(const float* __restrict__ X,
         const float* __restrict__ Wq, const float* __restrict__ bq,
         const float* __restrict__ Wk, const float* __restrict__ bk,
         const float* __restrict__ Wv, const float* __restrict__ bv,
         int mode)
{
    __shared__ uint2 AsI[2*BUF_STR];
    __shared__ uint2 BsI[2*BUF_STR];

    const int which = (mode == 1) ? 1 : ((blockIdx.x / 6) ? 2 : 0);
    const int nblk  = blockIdx.x % 6;
    const float* W    = (which == 0) ? Wq : (which == 1) ? Wk : Wv;
    const float* bias = (which == 0) ? bq : (which == 1) ? bk : bv;
    float* Cout = g_qkv + (size_t)which * NQKV;

    const int tid  = threadIdx.x;
    const int lane = tid & 31;
    const int warp = tid >> 5;
    const int g    = lane >> 2;
    const int t4   = lane & 3;
    const int wm   = (warp & 3) * 32;
    const int wn   = (warp >> 2) * 64;
    const int mBase = blockIdx.y * 128;
    const int nBase = nblk * 128;
    const int Ncol = ND, K = ND;

    const int aRow = tid >> 1;
    const int aKh  = tid & 1;
    const int bKh  = warp >> 2;
    const int bKg  = warp & 3;
    const int bN   = (tid & 31) * 4;

    long aOff = -1;
    {
        int m = mBase + aRow;
        if (m < NTOK) aOff = (long)m * K;
    }

    float ra[8], rb[8];
    auto loadAB = [&](int k0) {
        if (aOff >= 0) {
            const float4* p = (const float4*)(X + aOff + k0 + aKh*8);
            float4 v0 = p[0], v1 = p[1];
            ra[0]=v0.x; ra[1]=v0.y; ra[2]=v0.z; ra[3]=v0.w;
            ra[4]=v1.x; ra[5]=v1.y; ra[6]=v1.z; ra[7]=v1.w;
        } else {
            #pragma unroll
            for (int j = 0; j < 8; ++j) ra[j] = 0.f;
        }
        const float4 w0 = *(const float4*)(W + (long)(k0 + bKh*8 + bKg)     * Ncol + nBase + bN);
        const float4 w1 = *(const float4*)(W + (long)(k0 + bKh*8 + bKg + 4) * Ncol + nBase + bN);
        rb[0]=w0.x; rb[1]=w0.y; rb[2]=w0.z; rb[3]=w0.w;
        rb[4]=w1.x; rb[5]=w1.y; rb[6]=w1.z; rb[7]=w1.w;
    };
    auto stageAB = [&](int buf) {
        uint2* Ap = AsI + buf*BUF_STR + aKh*KH_STR + aRow;
        #pragma unroll
        for (int j = 0; j < 4; ++j)
            Ap[j*KG_STR] = make_uint2(f2tf32(ra[j]), f2tf32(ra[j+4]));
        uint2* Bp = BsI + buf*BUF_STR + bKh*KH_STR + bKg*KG_STR + bN;
        #pragma unroll
        for (int j = 0; j < 4; ++j)
            Bp[j] = make_uint2(f2tf32(rb[j]), f2tf32(rb[j+4]));
    };

    float acc[2][8][4];
    #pragma unroll
    for (int mt = 0; mt < 2; ++mt)
        #pragma unroll
        for (int nt = 0; nt < 8; ++nt)
            #pragma unroll
            for (int i = 0; i < 4; ++i) acc[mt][nt][i] = 0.f;

    loadAB(0);
    stageAB(0);
    __syncthreads();
    int cur = 0;

    for (int k0 = 0; k0 < K; k0 += 16) {
        const bool more = (k0 + 16) < K;
        if (more) loadAB(k0 + 16);

        #pragma unroll
        for (int ks = 0; ks < 2; ++ks) {
            const uint2* Ab = AsI + cur*BUF_STR + ks*KH_STR + t4*KG_STR;
            uint2 a00 = Ab[wm + g];
            uint2 a01 = Ab[wm + g + 8];
            uint2 a10 = Ab[wm + 16 + g];
            uint2 a11 = Ab[wm + 16 + g + 8];
            const uint2* Bb = BsI + cur*BUF_STR + ks*KH_STR + t4*KG_STR + wn;
            #pragma unroll
            for (int nt = 0; nt < 8; ++nt) {
                uint2 bb = Bb[nt*8 + g];
                mma_tf32(acc[0][nt], a00.x, a01.x, a00.y, a01.y, bb.x, bb.y);
                mma_tf32(acc[1][nt], a10.x, a11.x, a10.y, a11.y, bb.x, bb.y);
            }
        }
        if (more) {
            stageAB(cur ^ 1);
            __syncthreads();
            cur ^= 1;
        }
    }

    // epilogue: scatter to (B,H,S,HD)
    #pragma unroll
    for (int mt = 0; mt < 2; ++mt) {
        int r0 = mBase + wm + mt * 16 + g;
        #pragma unroll
        for (int nt = 0; nt < 8; ++nt) {
            int c0 = nBase + wn + nt * 8 + 2 * t4;
            #pragma unroll
            for (int half = 0; half < 2; ++half) {
                int m = r0 + half * 8;
                if (m < NTOK) {
                    int b = m / NS, s = m % NS;
                    int hh0 = c0 >> 6, hd0 = c0 & 63;
                    float* cp = Cout + ((((long)b * NH + hh0) * NS + s) * HD + hd0);
                    cp[0] = acc[mt][nt][half*2 + 0] + bias[c0];
                    cp[1] = acc[mt][nt][half*2 + 1] + bias[c0 + 1];
                }
            }
        }
    }
}

// =====================================================================
// adv_finish: per (b,h): p2 (64), p1 (256), entropy, per-bh losses.
// =====================================================================
__global__ void adv_finish(const float* __restrict__ a2, const float* __restrict__ b2)
{
    __shared__ float sm_p2[64];
    __shared__ float sred1[8], sred2[8];
    const int bh = blockIdx.x;
    const int tid = threadIdx.x, lane = tid & 31, w = tid >> 5;

    float l2 = 0.f;
    if (tid < 64) {
        const float* pp = g_part2 + ((size_t)bh * 64 + tid) * 8;
        float s = b2[0];
        #pragma unroll
        for (int i = 0; i < 8; ++i) s += pp[i];
        float p = 1.f / (1.f + __expf(-s));
        sm_p2[tid] = p;
        l2 = __logf(fmaxf(1.f - p, EPSV));
    }
    float l1;
    float p1v;
    {
        const float* pp = g_part1 + ((size_t)bh * 256 + tid) * 8;
        float s = a2[0];
        #pragma unroll
        for (int i = 0; i < 8; ++i) s += pp[i];
        p1v = 1.f / (1.f + __expf(-s));
        l1 = __logf(fmaxf(1.f - p1v, EPSV));
    }
    #pragma unroll
    for (int o = 16; o > 0; o >>= 1) {
        l1 += __shfl_xor_sync(0xffffffffu, l1, o);
        l2 += __shfl_xor_sync(0xffffffffu, l2, o);
    }
    if (lane == 0) { sred1[w] = l1; sred2[w] = l2; }
    __syncthreads();

    {
        int t = tid;
        int gr = t >> 4, gc = t & 15;
        int m  = (gr >> 1) * 8 + (gc >> 1);
        float ad  = (1.f - LAMDA) * p1v + LAMDA * sm_p2[m];
        float ent = -ad * __log2f(ad + EPSV) - (1.f - ad) * __log2f(1.f - ad + EPSV);
        g_ent[bh * NS + 1 + t] = ent;
    }
    if (tid == 0) {
        g_ent[bh * NS] = 1.f;
        float s1 = 0.f, s2 = 0.f;
        #pragma unroll
        for (int i = 0; i < 8; ++i) { s1 += sred1[i]; s2 += sred2[i]; }
        g_loss1[bh] = s1;
        g_loss2[bh] = s2;
    }
}

// =====================================================================
// Tensor-core attention: one block per (b,h), 256 threads (8 warps).
// K packed as uint2 (d, d+4) pairs: K2[tok][32], stride 36 uint2.
// V^T packed as uint2 (tok, tok+4) pairs: VT2[d][132], stride 132 uint2.
// All MMA B-fragment loads are single LDS.64, bank-conflict-free.
// =====================================================================
#define K2_STR 36
#define VT2_STR 132

__global__ void __launch_bounds__(256, 1)
attn_kernel()
{
    extern __shared__ uint2 smu2[];
    uint2*  K2   = smu2;                         // 264*36
    uint2*  VT2  = smu2 + 264*K2_STR;            // 64*132
    float*  entS = (float*)(VT2 + 64*VT2_STR);   // 264
    float*  sP   = entS + 264;                   // 264

    const int bh   = blockIdx.x;
    const int tid  = threadIdx.x;
    const int lane = tid & 31;
    const int w    = tid >> 5;
    const int g    = lane >> 2;
    const int t4   = lane & 3;

    const float* qb = g_qkv + (size_t)bh * NS * HD;
    const float* kb = g_qkv + (size_t)NQKV + (size_t)bh * NS * HD;
    const float* vb = g_qkv + (size_t)2*NQKV + (size_t)bh * NS * HD;

    // ---- stage K2: thread handles (tok, q): q -> d pair (8*(q>>2)+(q&3), +4)
    for (int i = tid; i < 264*32; i += 256) {
        int tok = i >> 5, q = i & 31;
        int d0 = 8*(q >> 2) + (q & 3);
        uint2 val = make_uint2(0u, 0u);
        if (tok < NS) {
            val.x = f2tf32(kb[tok*64 + d0]);
            val.y = f2tf32(kb[tok*64 + d0 + 4]);
        }
        K2[tok*K2_STR + q] = val;
    }
    // ---- stage VT2: thread handles (p, d): p -> tok pair (8*(p>>2)+(p&3), +4)
    for (int i = tid; i < 132*64; i += 256) {
        int d = i & 63, p = i >> 6;
        int tx = 8*(p >> 2) + (p & 3);
        int ty = tx + 4;
        uint2 val = make_uint2(0u, 0u);
        if (tx < NS) val.x = f2tf32(vb[tx*64 + d]);
        if (ty < NS) val.y = f2tf32(vb[ty*64 + d]);
        VT2[d*VT2_STR + p] = val;
    }
    for (int i = tid; i < 264; i += 256) {
        entS[i] = (i < NS) ? g_ent[bh*NS + i] : 0.f;
        sP[i]   = 0.f;
    }
    __syncthreads();

    const int b = bh / NH, h = bh % NH;
    const int qbase = lane & ~3;

    #pragma unroll
    for (int ti = 0; ti < 2; ++ti) {
        const int tile = w*2 + ti;
        const int m0   = tile * 16;

        unsigned aq[8][4];
        const float* q0 = qb + (m0 + g) * 64;
        const float* q1 = qb + (m0 + g + 8) * 64;
        #pragma unroll
        for (int ks = 0; ks < 8; ++ks) {
            aq[ks][0] = f2tf32(q0[ks*8 + t4]);
            aq[ks][1] = f2tf32(q1[ks*8 + t4]);
            aq[ks][2] = f2tf32(q0[ks*8 + t4 + 4]);
            aq[ks][3] = f2tf32(q1[ks*8 + t4 + 4]);
        }

        // ---- S = Q @ K^T : B-fragment = one LDS.64 from K2
        float sf[33][4];
        #pragma unroll
        for (int nt = 0; nt < 33; ++nt) {
            float c4[4] = {0.f, 0.f, 0.f, 0.f};
            const uint2* kr = K2 + (nt*8 + g) * K2_STR + t4;
            #pragma unroll
            for (int ks = 0; ks < 8; ++ks) {
                uint2 bb = kr[ks*4];
                mma_tf32(c4, aq[ks][0], aq[ks][1], aq[ks][2], aq[ks][3],
                         bb.x, bb.y);
            }
            sf[nt][0] = c4[0] * 0.125f;
            sf[nt][1] = c4[1] * 0.125f;
            sf[nt][2] = c4[2] * 0.125f;
            sf[nt][3] = c4[3] * 0.125f;
        }

        // ---- softmax in fragments
        float mx0 = -1e30f, mx1 = -1e30f;
        #pragma unroll
        for (int nt = 0; nt < 32; ++nt) {
            mx0 = fmaxf(mx0, fmaxf(sf[nt][0], sf[nt][1]));
            mx1 = fmaxf(mx1, fmaxf(sf[nt][2], sf[nt][3]));
        }
        if (t4 == 0) {
            mx0 = fmaxf(mx0, sf[32][0]);
            mx1 = fmaxf(mx1, sf[32][2]);
        }
        mx0 = fmaxf(mx0, __shfl_xor_sync(0xffffffffu, mx0, 1));
        mx0 = fmaxf(mx0, __shfl_xor_sync(0xffffffffu, mx0, 2));
        mx1 = fmaxf(mx1, __shfl_xor_sync(0xffffffffu, mx1, 1));
        mx1 = fmaxf(mx1, __shfl_xor_sync(0xffffffffu, mx1, 2));

        float sum0 = 0.f, sum1 = 0.f;
        #pragma unroll
        for (int nt = 0; nt < 32; ++nt) {
            sf[nt][0] = __expf(sf[nt][0] - mx0); sum0 += sf[nt][0];
            sf[nt][1] = __expf(sf[nt][1] - mx0); sum0 += sf[nt][1];
            sf[nt][2] = __expf(sf[nt][2] - mx1); sum1 += sf[nt][2];
            sf[nt][3] = __expf(sf[nt][3] - mx1); sum1 += sf[nt][3];
        }
        {
            float e0 = (t4 == 0) ? __expf(sf[32][0] - mx0) : 0.f;
            float e2 = (t4 == 0) ? __expf(sf[32][2] - mx1) : 0.f;
            sf[32][0] = e0; sum0 += e0;
            sf[32][1] = 0.f;
            sf[32][2] = e2; sum1 += e2;
            sf[32][3] = 0.f;
        }
        sum0 += __shfl_xor_sync(0xffffffffu, sum0, 1);
        sum0 += __shfl_xor_sync(0xffffffffu, sum0, 2);
        sum1 += __shfl_xor_sync(0xffffffffu, sum1, 1);
        sum1 += __shfl_xor_sync(0xffffffffu, sum1, 2);
        const float inv0 = 1.f / sum0, inv1 = 1.f / sum1;

        const bool entRow = (tile == 0) && (g == 0);
        #pragma unroll
        for (int nt = 0; nt < 33; ++nt) {
            sf[nt][0] *= inv0;
            sf[nt][1] *= inv0;
            sf[nt][2] *= inv1;
            sf[nt][3] *= inv1;
            if (entRow) {
                sf[nt][0] *= entS[nt*8 + 2*t4];
                sf[nt][1] *= entS[nt*8 + 2*t4 + 1];
            }
        }

        // ---- ctx = P @ V^T : B-fragment = one LDS.64 from VT2
        float oc[8][4];
        #pragma unroll
        for (int nt = 0; nt < 8; ++nt)
            #pragma unroll
            for (int i = 0; i < 4; ++i) oc[nt][i] = 0.f;

        const int l1 = qbase + (t4 >> 1);
        const int l2 = l1 + 2;
        const bool odd = (t4 & 1);

        #pragma unroll
        for (int ks = 0; ks < 33; ++ks) {
            unsigned u0 = f2tf32(sf[ks][0]);
            unsigned u1 = f2tf32(sf[ks][1]);
            unsigned u2 = f2tf32(sf[ks][2]);
            unsigned u3 = f2tf32(sf[ks][3]);
            unsigned x0a = __shfl_sync(0xffffffffu, u0, l1);
            unsigned x0b = __shfl_sync(0xffffffffu, u1, l1);
            unsigned x1a = __shfl_sync(0xffffffffu, u2, l1);
            unsigned x1b = __shfl_sync(0xffffffffu, u3, l1);
            unsigned y0a = __shfl_sync(0xffffffffu, u0, l2);
            unsigned y0b = __shfl_sync(0xffffffffu, u1, l2);
            unsigned y1a = __shfl_sync(0xffffffffu, u2, l2);
            unsigned y1b = __shfl_sync(0xffffffffu, u3, l2);
            unsigned a0 = odd ? x0b : x0a;
            unsigned a1 = odd ? x1b : x1a;
            unsigned a2 = odd ? y0b : y0a;
            unsigned a3 = odd ? y1b : y1a;
            #pragma unroll
            for (int nt = 0; nt < 8; ++nt) {
                uint2 bb = VT2[(nt*8 + g) * VT2_STR + ks*4 + t4];
                mma_tf32(oc[nt], a0, a1, a2, a3, bb.x, bb.y);
            }
        }

        float* base0 = g_ctx + ((size_t)(b*NS + m0 + g    )) * ND + h*HD;
        float* base1 = g_ctx + ((size_t)(b*NS + m0 + g + 8)) * ND + h*HD;
        #pragma unroll
        for (int nt = 0; nt < 8; ++nt) {
            int c0 = nt*8 + 2*t4;
            base0[c0]     = oc[nt][0];
            base0[c0 + 1] = oc[nt][1];
            base1[c0]     = oc[nt][2];
            base1[c0 + 1] = oc[nt][3];
        }
    }

    // ---- query 256: scalar path on warp 7 (packed layouts)
    if (w == 7) {
        float q[64];
        #pragma unroll
        for (int d = 0; d < 64; ++d) q[d] = qb[256*64 + d];

        float sc[9];
        #pragma unroll
        for (int c = 0; c < 9; ++c) {
            int kt = lane + 32*c;
            float acc = -1e30f;
            if (kt <= 256) {
                acc = 0.f;
                const uint2* kr2 = K2 + kt * K2_STR;
                #pragma unroll
                for (int p = 0; p < 32; ++p) {
                    int d0 = 8*(p >> 2) + (p & 3);
                    uint2 kk = kr2[p];
                    acc = fmaf(q[d0],     __uint_as_float(kk.x), acc);
                    acc = fmaf(q[d0 + 4], __uint_as_float(kk.y), acc);
                }
                acc *= 0.125f;
            }
            sc[c] = acc;
        }
        float mx = sc[0];
        #pragma unroll
        for (int c = 1; c < 9; ++c) mx = fmaxf(mx, sc[c]);
        #pragma unroll
        for (int o = 16; o > 0; o >>= 1) mx = fmaxf(mx, __shfl_xor_sync(0xffffffffu, mx, o));
        float sum = 0.f;
        #pragma unroll
        for (int c = 0; c < 9; ++c) {
            int kt = lane + 32*c;
            float e = (kt <= 256) ? __expf(sc[c] - mx) : 0.f;
            sc[c] = e; sum += e;
        }
        #pragma unroll
        for (int o = 16; o > 0; o >>= 1) sum += __shfl_xor_sync(0xffffffffu, sum, o);
        float inv = 1.f / sum;
        #pragma unroll
        for (int c = 0; c < 9; ++c) {
            int kt = lane + 32*c;
            if (kt <= 256) sP[kt] = sc[c] * inv;
        }
        __syncwarp();

        float a0 = 0.f, a1 = 0.f;
        const uint2* v0 = VT2 + (size_t)lane * VT2_STR;
        const uint2* v1 = VT2 + (size_t)(lane + 32) * VT2_STR;
        for (int p = 0; p < 132; ++p) {
            int tx = 8*(p >> 2) + (p & 3);
            float px = sP[tx], py = sP[tx + 4];
            uint2 b0 = v0[p], b1 = v1[p];
            a0 = fmaf(px, __uint_as_float(b0.x), a0);
            a0 = fmaf(py, __uint_as_float(b0.y), a0);
            a1 = fmaf(px, __uint_as_float(b1.x), a1);
            a1 = fmaf(py, __uint_as_float(b1.y), a1);
        }
        float* cp = g_ctx + ((size_t)(b*NS + 256)) * ND + h*HD;
        cp[lane]      = a0;
        cp[lane + 32] = a1;
    }
}

// =====================================================================
// Final deterministic loss reduction
// =====================================================================
__global__ void loss_kernel(float* __restrict__ out)
{
    __shared__ float s1[256], s2[256];
    int tid = threadIdx.x;
    float a = 0.f, b = 0.f;
    for (int i = tid; i < NBH; i += 256) { a += g_loss1[i]; b += g_loss2[i]; }
    s1[tid] = a; s2[tid] = b;
    __syncthreads();
    for (int o = 128; o > 0; o >>= 1) {
        if (tid < o) { s1[tid] += s1[tid + o]; s2[tid] += s2[tid + o]; }
        __syncthreads();
    }
    if (tid == 0)
        out[0] = -s1[0] / ((float)NBH * 256.f) - s2[0] / ((float)NBH * 64.f);
}

// =====================================================================
// Launch: K projection first, then fork adv path onto side stream while
// Q/V projections run on the main stream; join before attention.
// =====================================================================
extern "C" void kernel_launch(void* const* d_in, const int* in_sizes, int n_in,
                              void* d_out, int out_size)
{
    const float* X  = (const float*)d_in[0];
    const float* Wq = (const float*)d_in[1];
    const float* bq = (const float*)d_in[2];
    const float* Wk = (const float*)d_in[3];
    const float* bk = (const float*)d_in[4];
    const float* Wv = (const float*)d_in[5];
    const float* bv = (const float*)d_in[6];
    const float* Wo = (const float*)d_in[7];
    const float* bo = (const float*)d_in[8];
    const float* A1 = (const float*)d_in[9];
    const float* a1 = (const float*)d_in[10];
    const float* A2 = (const float*)d_in[11];
    const float* a2 = (const float*)d_in[12];
    const float* B1 = (const float*)d_in[13];
    const float* b1 = (const float*)d_in[14];
    const float* B2 = (const float*)d_in[15];
    const float* b2 = (const float*)d_in[16];
    float* out = (float*)d_out;

    float *qkv = nullptr, *ctx = nullptr, *pt1 = nullptr, *pt2 = nullptr;
    cudaGetSymbolAddress((void**)&qkv, g_qkv);
    cudaGetSymbolAddress((void**)&ctx, g_ctx);
    cudaGetSymbolAddress((void**)&pt1, g_part1);
    cudaGetSymbolAddress((void**)&pt2, g_part2);
    float* kbase = qkv + NQKV;

    static cudaStream_t s2 = nullptr;
    static cudaEvent_t evK = nullptr, evAdv = nullptr;
    if (s2 == nullptr) {
        cudaStreamCreateWithFlags(&s2, cudaStreamNonBlocking);
        cudaEventCreateWithFlags(&evK,  cudaEventDisableTiming);
        cudaEventCreateWithFlags(&evAdv, cudaEventDisableTiming);
    }

    const int ATTN_SMEM = (264*K2_STR + 64*VT2_STR) * 8 + (264 + 264) * 4; // 145728
    cudaFuncSetAttribute(attn_kernel, cudaFuncAttributeMaxDynamicSharedMemorySize, ATTN_SMEM);

    // 1) K projection on main stream
    gemm_qkv<<<dim3(6, (NTOK + 127)/128), 256>>>(X, Wq, bq, Wk, bk, Wv, bv, 1);
    cudaEventRecord(evK, 0);

    // 2) fork: adversarial path on s2 (depends only on K)
    cudaStreamWaitEvent(s2, evK, 0);
    gemm_tc<2,3><<<dim3(4, (NBH*256)/128), 256, 0, s2>>>(kbase, A1, a1, A2, pt1, NBH*256, 512, 64);
    gemm_tc<3,3><<<dim3(4, (NBH*64)/128),  256, 0, s2>>>(kbase, B1, b1, B2, pt2, NBH*64,  512, 256);
    adv_finish<<<NBH, 256, 0, s2>>>(a2, b2);
    if (out_size > NQKV)
        loss_kernel<<<1, 256, 0, s2>>>(out + (out_size - 1));
    cudaEventRecord(evAdv, s2);

    // 3) Q and V projections on main stream (concurrent with s2)
    gemm_qkv<<<dim3(12, (NTOK + 127)/128), 256>>>(X, Wq, bq, Wk, bk, Wv, bv, 0);

    // 4) join, then attention + output projection
    cudaStreamWaitEvent(0, evAdv, 0);
    attn_kernel<<<NBH, 256, ATTN_SMEM>>>();
    gemm_tc<0,0><<<dim3(6, (NTOK + 127)/128), 256>>>(ctx, Wo, bo, nullptr, out, NTOK, ND, ND);
}